// round 1
// baseline (speedup 1.0000x reference)
#include <cuda_runtime.h>
#include <math.h>

#define Bsz 2
#define Ssz 2048
#define Dsz 1024
#define Hn  16
#define DHs 64
#define Mrows (Bsz*Ssz)

// Scratch (static device globals: allowed; no runtime allocation)
__device__ float g_q[Mrows*Dsz];
__device__ float g_k[Mrows*Dsz];
__device__ float g_v[Mrows*Dsz];
__device__ float g_o[Mrows*Dsz];

// ---------------------------------------------------------------------------
// GEMM: out = (X[M,K] @ W[K,N] + bias[N]) * scale
// HEAD_SPLIT=1 writes [B,H,S,DH] layout, else plain row-major [M,N].
// 64x64 tile, BK=16, 256 threads, 4x4 per thread.
// ---------------------------------------------------------------------------
template<int HEAD_SPLIT>
__global__ void gemm_bias_kernel(const float* __restrict__ X,
                                 const float* __restrict__ W,
                                 const float* __restrict__ bias,
                                 float* __restrict__ out,
                                 float scale)
{
    const int K = Dsz, N = Dsz;
    __shared__ float Xs[16][68];   // transposed: Xs[k][m]
    __shared__ float Ws[16][68];   // Ws[k][n]
    const int tid = threadIdx.x;
    const int tx = tid & 15, ty = tid >> 4;
    const int row0 = blockIdx.y * 64, col0 = blockIdx.x * 64;

    float acc[4][4] = {};
    for (int k0 = 0; k0 < K; k0 += 16) {
        #pragma unroll
        for (int i = tid; i < 64*16; i += 256) {
            int r = i >> 4, c = i & 15;
            Xs[c][r] = X[(row0 + r) * K + k0 + c];
        }
        #pragma unroll
        for (int i = tid; i < 16*64; i += 256) {
            int r = i >> 6, c = i & 63;
            Ws[r][c] = W[(k0 + r) * N + col0 + c];
        }
        __syncthreads();
        #pragma unroll
        for (int kk = 0; kk < 16; kk++) {
            float4 xv = *(const float4*)&Xs[kk][ty*4];
            float4 wv = *(const float4*)&Ws[kk][tx*4];
            float xa[4] = {xv.x, xv.y, xv.z, xv.w};
            float wa[4] = {wv.x, wv.y, wv.z, wv.w};
            #pragma unroll
            for (int i = 0; i < 4; i++)
                #pragma unroll
                for (int j = 0; j < 4; j++)
                    acc[i][j] += xa[i] * wa[j];
        }
        __syncthreads();
    }

    #pragma unroll
    for (int i = 0; i < 4; i++) {
        int r = row0 + ty*4 + i;
        #pragma unroll
        for (int j = 0; j < 4; j++) {
            int c = col0 + tx*4 + j;
            float v = (acc[i][j] + bias[c]) * scale;
            if (HEAD_SPLIT) {
                int b = r / Ssz, s = r % Ssz;
                int h = c / DHs, dh = c & (DHs-1);
                out[(((b*Hn + h) * Ssz) + s) * DHs + dh] = v;
            } else {
                out[r * Dsz + c] = v;
            }
        }
    }
}

// ---------------------------------------------------------------------------
// Flash attention: per block one (b, h, 64-row Q tile); loop over 64-row KV
// tiles with online softmax. Q pre-scaled by 1/sqrt(DH) at projection time.
// smem: Qs_t[64][68] (d-major), KP[64][68] (K transposed, then P), Vs[64][64].
// Writes O in [B,S,H,DH] (== [M,D] row-major) for the final projection.
// ---------------------------------------------------------------------------
__global__ void attn_kernel(const float* __restrict__ Q,
                            const float* __restrict__ K,
                            const float* __restrict__ V,
                            float* __restrict__ O)
{
    extern __shared__ float sm[];
    float* Qs = sm;                 // [64][68]  Qs[d*68 + q]
    float* KP = sm + 64*68;         // [64][68]  K: KP[d*68 + k];  P: KP[q*68 + k]
    float* Vs = sm + 2*64*68;       // [64][64]  Vs[k*64 + dh]

    const int tid = threadIdx.x;
    const int tx = tid & 15, ty = tid >> 4;
    const int q0 = blockIdx.x * 64;
    const int h = blockIdx.y, b = blockIdx.z;
    const long base = ((long)(b*Hn + h)) * Ssz * DHs;
    const float* Qg = Q + base;
    const float* Kg = K + base;
    const float* Vg = V + base;

    // Load Q tile transposed (d-major)
    #pragma unroll
    for (int i = tid; i < 64*64; i += 256) {
        int r = i >> 6, d = i & 63;
        Qs[d*68 + r] = Qg[(q0 + r)*DHs + d];
    }

    float m[4], l[4], o[4][4];
    #pragma unroll
    for (int i = 0; i < 4; i++) {
        m[i] = -1e30f; l[i] = 0.0f;
        #pragma unroll
        for (int j = 0; j < 4; j++) o[i][j] = 0.0f;
    }

    for (int t0 = 0; t0 < Ssz; t0 += 64) {
        __syncthreads();   // prev tile's P/V reads done; Q store visible (1st iter via 2nd sync)
        #pragma unroll
        for (int i = tid; i < 64*64; i += 256) {
            int r = i >> 6, d = i & 63;
            KP[d*68 + r] = Kg[(t0 + r)*DHs + d];     // K transposed
        }
        #pragma unroll
        for (int i = tid; i < 64*64; i += 256) {
            int r = i >> 6, d = i & 63;
            Vs[r*64 + d] = Vg[(t0 + r)*DHs + d];
        }
        __syncthreads();

        // S = Q K^T (Q already scaled)
        float s[4][4] = {};
        #pragma unroll 16
        for (int d = 0; d < 64; d++) {
            float4 qv = *(const float4*)&Qs[d*68 + ty*4];
            float4 kv = *(const float4*)&KP[d*68 + tx*4];
            float qa[4] = {qv.x, qv.y, qv.z, qv.w};
            float ka[4] = {kv.x, kv.y, kv.z, kv.w};
            #pragma unroll
            for (int i = 0; i < 4; i++)
                #pragma unroll
                for (int j = 0; j < 4; j++)
                    s[i][j] += qa[i] * ka[j];
        }

        // Row max (4 local cols, then 16-lane butterfly)
        float rm[4];
        #pragma unroll
        for (int i = 0; i < 4; i++)
            rm[i] = fmaxf(fmaxf(s[i][0], s[i][1]), fmaxf(s[i][2], s[i][3]));
        #pragma unroll
        for (int off = 1; off < 16; off <<= 1)
            #pragma unroll
            for (int i = 0; i < 4; i++)
                rm[i] = fmaxf(rm[i], __shfl_xor_sync(0xffffffffu, rm[i], off));

        float alpha[4], p[4][4], rs[4];
        #pragma unroll
        for (int i = 0; i < 4; i++) {
            float mn = fmaxf(m[i], rm[i]);
            alpha[i] = __expf(m[i] - mn);
            m[i] = mn;
        }
        #pragma unroll
        for (int i = 0; i < 4; i++) {
            #pragma unroll
            for (int j = 0; j < 4; j++)
                p[i][j] = __expf(s[i][j] - m[i]);
            rs[i] = (p[i][0] + p[i][1]) + (p[i][2] + p[i][3]);
        }
        #pragma unroll
        for (int off = 1; off < 16; off <<= 1)
            #pragma unroll
            for (int i = 0; i < 4; i++)
                rs[i] += __shfl_xor_sync(0xffffffffu, rs[i], off);
        #pragma unroll
        for (int i = 0; i < 4; i++) {
            l[i] = l[i] * alpha[i] + rs[i];
            #pragma unroll
            for (int j = 0; j < 4; j++) o[i][j] *= alpha[i];
        }

        __syncthreads();   // everyone done reading K from KP
        #pragma unroll
        for (int i = 0; i < 4; i++)
            #pragma unroll
            for (int j = 0; j < 4; j++)
                KP[(ty*4 + i)*68 + tx*4 + j] = p[i][j];
        __syncthreads();

        // O += P @ V
        #pragma unroll 16
        for (int kk = 0; kk < 64; kk++) {
            float4 vv = *(const float4*)&Vs[kk*64 + tx*4];
            float va[4] = {vv.x, vv.y, vv.z, vv.w};
            float pa[4];
            #pragma unroll
            for (int i = 0; i < 4; i++) pa[i] = KP[(ty*4 + i)*68 + kk];
            #pragma unroll
            for (int i = 0; i < 4; i++)
                #pragma unroll
                for (int j = 0; j < 4; j++)
                    o[i][j] += pa[i] * va[j];
        }
    }

    // Normalize and write O in [B,S,H*DH] layout
    #pragma unroll
    for (int i = 0; i < 4; i++) {
        int q = q0 + ty*4 + i;
        float inv = 1.0f / l[i];
        #pragma unroll
        for (int j = 0; j < 4; j++) {
            int dh = tx*4 + j;
            O[((long)(b*Ssz + q)) * Dsz + h*DHs + dh] = o[i][j] * inv;
        }
    }
}

// ---------------------------------------------------------------------------

static const int ATTN_SMEM = (2*64*68 + 64*64) * (int)sizeof(float);  // 51200 B

extern "C" void kernel_launch(void* const* d_in, const int* in_sizes, int n_in,
                              void* d_out, int out_size)
{
    (void)in_sizes; (void)n_in; (void)out_size;
    const float* queries = (const float*)d_in[0];
    const float* keys    = (const float*)d_in[1];
    const float* values  = (const float*)d_in[2];
    const float* Wq = (const float*)d_in[3];
    const float* bq = (const float*)d_in[4];
    const float* Wk = (const float*)d_in[5];
    const float* bk = (const float*)d_in[6];
    const float* Wv = (const float*)d_in[7];
    const float* bv = (const float*)d_in[8];
    const float* Wo = (const float*)d_in[9];
    const float* bo = (const float*)d_in[10];
    float* out = (float*)d_out;

    void *pq, *pk, *pv, *po;
    cudaGetSymbolAddress(&pq, g_q);
    cudaGetSymbolAddress(&pk, g_k);
    cudaGetSymbolAddress(&pv, g_v);
    cudaGetSymbolAddress(&po, g_o);

    cudaFuncSetAttribute(attn_kernel,
                         cudaFuncAttributeMaxDynamicSharedMemorySize, ATTN_SMEM);

    dim3 ggrid(Dsz/64, Mrows/64);   // (16, 64)
    const float qscale = 0.125f;    // 1/sqrt(DH)

    gemm_bias_kernel<1><<<ggrid, 256>>>(queries, Wq, bq, (float*)pq, qscale);
    gemm_bias_kernel<1><<<ggrid, 256>>>(keys,    Wk, bk, (float*)pk, 1.0f);
    gemm_bias_kernel<1><<<ggrid, 256>>>(values,  Wv, bv, (float*)pv, 1.0f);

    dim3 agrid(Ssz/64, Hn, Bsz);    // (32, 16, 2)
    attn_kernel<<<agrid, 256, ATTN_SMEM>>>((const float*)pq, (const float*)pk,
                                           (const float*)pv, (float*)po);

    gemm_bias_kernel<0><<<ggrid, 256>>>((const float*)po, Wo, bo, out, 1.0f);
}

// round 2
// speedup vs baseline: 3.3629x; 3.3629x over previous
#include <cuda_runtime.h>
#include <math.h>

#define Bsz 2
#define Ssz 2048
#define Dsz 1024
#define Hn  16
#define DHs 64
#define Mrows (Bsz*Ssz)

// Scratch (static device globals: allowed; no runtime allocation)
__device__ float g_q[Mrows*Dsz];
__device__ float g_k[Mrows*Dsz];
__device__ float g_v[Mrows*Dsz];
__device__ float g_o[Mrows*Dsz];

// ---------------------------------------------------------------------------
// helpers
// ---------------------------------------------------------------------------
__device__ __forceinline__ unsigned f2tf32(float x) {
    unsigned r;
    asm("cvt.rna.tf32.f32 %0, %1;" : "=r"(r) : "f"(x));
    return r;
}

__device__ __forceinline__ void mma_tf32(float* c, const unsigned* a, const unsigned* b) {
    asm volatile(
        "mma.sync.aligned.m16n8k8.row.col.f32.tf32.tf32.f32 "
        "{%0,%1,%2,%3}, {%4,%5,%6,%7}, {%8,%9}, {%0,%1,%2,%3};"
        : "+f"(c[0]), "+f"(c[1]), "+f"(c[2]), "+f"(c[3])
        : "r"(a[0]), "r"(a[1]), "r"(a[2]), "r"(a[3]), "r"(b[0]), "r"(b[1]));
}

__device__ __forceinline__ void cp_async16(void* smem, const void* gmem) {
    unsigned s = (unsigned)__cvta_generic_to_shared(smem);
    asm volatile("cp.async.cg.shared.global [%0], [%1], 16;" :: "r"(s), "l"(gmem));
}
#define CP_COMMIT() asm volatile("cp.async.commit_group;")
#define CP_WAIT1()  asm volatile("cp.async.wait_group 1;")
#define CP_WAIT0()  asm volatile("cp.async.wait_group 0;")

// ---------------------------------------------------------------------------
// TF32 GEMM: out = (X[M,1024] @ W[1024,1024] + bias) * scale
// 128x128 block tile, BK=32, 256 threads (8 warps, 4M x 2N), cp.async 2-stage.
// smem pitches: A 36 floats, B 132 floats (conflict-free fragment loads).
// ---------------------------------------------------------------------------
#define A_PITCH 36
#define B_PITCH 132
#define GEMM_SMEM ((2*128*A_PITCH + 2*32*B_PITCH) * 4)

template<int HEAD_SPLIT>
__global__ __launch_bounds__(256, 2)
void gemm_tf32(const float* __restrict__ X, const float* __restrict__ W,
               const float* __restrict__ bias, float* __restrict__ out,
               float scale)
{
    extern __shared__ float sm[];
    float* As = sm;                       // [2][128][36]
    float* Bs = sm + 2*128*A_PITCH;       // [2][32][132]

    const int tid  = threadIdx.x;
    const int lane = tid & 31;
    const int warp = tid >> 5;
    const int g  = lane >> 2;            // groupID 0..7
    const int tg = lane & 3;             // threadID_in_group 0..3
    const int m0w = (warp >> 1) * 32;
    const int n0w = (warp & 1) * 64;
    const int row0 = blockIdx.y * 128;
    const int col0 = blockIdx.x * 128;

    float c[2][8][4] = {};

    auto load_stage = [&](int kt, int p) {
        float* Ad = As + p*128*A_PITCH;
        float* Bd = Bs + p*32*B_PITCH;
        #pragma unroll
        for (int i = 0; i < 4; i++) {           // A: 1024 float4
            int idx = tid + i*256;
            int r = idx >> 3, c4 = idx & 7;
            cp_async16(&Ad[r*A_PITCH + c4*4], &X[(size_t)(row0 + r)*Dsz + kt*32 + c4*4]);
        }
        #pragma unroll
        for (int i = 0; i < 4; i++) {           // B: 1024 float4
            int idx = tid + i*256;
            int r = idx >> 5, c4 = idx & 31;
            cp_async16(&Bd[r*B_PITCH + c4*4], &W[(size_t)(kt*32 + r)*Dsz + col0 + c4*4]);
        }
    };

    load_stage(0, 0);
    CP_COMMIT();

    const int NT = Dsz / 32;   // 32 k-tiles
    for (int kt = 0; kt < NT; kt++) {
        int p = kt & 1;
        if (kt + 1 < NT) {
            load_stage(kt + 1, p ^ 1);
            CP_COMMIT();
            CP_WAIT1();
        } else {
            CP_WAIT0();
        }
        __syncthreads();

        const float* Ap = As + p*128*A_PITCH;
        const float* Bp = Bs + p*32*B_PITCH;
        #pragma unroll
        for (int ks = 0; ks < 4; ks++) {
            unsigned a[2][4], b[8][2];
            #pragma unroll
            for (int mi = 0; mi < 2; mi++) {
                int r = m0w + mi*16 + g;
                int kc = ks*8 + tg;
                a[mi][0] = f2tf32(Ap[r*A_PITCH + kc]);
                a[mi][1] = f2tf32(Ap[(r+8)*A_PITCH + kc]);
                a[mi][2] = f2tf32(Ap[r*A_PITCH + kc + 4]);
                a[mi][3] = f2tf32(Ap[(r+8)*A_PITCH + kc + 4]);
            }
            #pragma unroll
            for (int ni = 0; ni < 8; ni++) {
                int nn = n0w + ni*8 + g;
                b[ni][0] = f2tf32(Bp[(ks*8 + tg)*B_PITCH + nn]);
                b[ni][1] = f2tf32(Bp[(ks*8 + tg + 4)*B_PITCH + nn]);
            }
            #pragma unroll
            for (int mi = 0; mi < 2; mi++)
                #pragma unroll
                for (int ni = 0; ni < 8; ni++)
                    mma_tf32(c[mi][ni], a[mi], b[ni]);
        }
        __syncthreads();
    }

    // epilogue: bias + scale, float2 stores
    #pragma unroll
    for (int mi = 0; mi < 2; mi++) {
        #pragma unroll
        for (int ni = 0; ni < 8; ni++) {
            int cc = col0 + n0w + ni*8 + 2*tg;
            float bx = bias[cc], by = bias[cc+1];
            #pragma unroll
            for (int rr = 0; rr < 2; rr++) {
                int r = row0 + m0w + mi*16 + g + rr*8;
                float2 v;
                v.x = (c[mi][ni][rr*2+0] + bx) * scale;
                v.y = (c[mi][ni][rr*2+1] + by) * scale;
                if (HEAD_SPLIT) {
                    int b_ = r >> 11, s_ = r & (Ssz-1);
                    int h_ = cc >> 6, dh = cc & (DHs-1);
                    *(float2*)&out[(((size_t)(b_*Hn + h_) * Ssz + s_) * DHs) + dh] = v;
                } else {
                    *(float2*)&out[(size_t)r * Dsz + cc] = v;
                }
            }
        }
    }
}

// ---------------------------------------------------------------------------
// Flash attention, tf32 MMA. 128-row Q tile, 64-row KV tiles, 8 warps.
// Each warp owns 16 q-rows (one m16 tile). S and PV via m16n8k8 tf32.
// smem: Qs[128][68], Ks[64][68], Vs[64][68], Ps[128][68]   (104,448 B)
// ---------------------------------------------------------------------------
#define P68 68
#define ATTN_SMEM ((128*P68 + 64*P68 + 64*P68 + 128*P68) * 4)

__global__ __launch_bounds__(256, 2)
void attn_mma(const float* __restrict__ Q, const float* __restrict__ K,
              const float* __restrict__ V, float* __restrict__ O)
{
    extern __shared__ float sm[];
    float* Qs = sm;                  // [128][68]
    float* Ks = Qs + 128*P68;        // [64][68]
    float* Vs = Ks + 64*P68;         // [64][68]
    float* Ps = Vs + 64*P68;         // [128][68]

    const int tid  = threadIdx.x;
    const int lane = tid & 31;
    const int warp = tid >> 5;
    const int g  = lane >> 2;
    const int tg = lane & 3;
    const int m0w = warp * 16;       // warp's q-row base within tile

    const int q0 = blockIdx.x * 128;
    const int h = blockIdx.y, b = blockIdx.z;
    const size_t base = ((size_t)(b*Hn + h)) * Ssz * DHs;
    const float* Qg = Q + base;
    const float* Kg = K + base;
    const float* Vg = V + base;

    // load Q tile (128x64), float4
    #pragma unroll
    for (int i = 0; i < 8; i++) {
        int idx = tid + i*256;
        int r = idx >> 4, c4 = idx & 15;
        *(float4*)&Qs[r*P68 + c4*4] = *(const float4*)&Qg[(size_t)(q0 + r)*DHs + c4*4];
    }

    float o[8][4] = {};
    float m0 = -1e30f, m1 = -1e30f, l0 = 0.0f, l1 = 0.0f;

    for (int t0 = 0; t0 < Ssz; t0 += 64) {
        __syncthreads();   // prior iter's Ks/Vs reads complete (also orders Qs on iter 0)
        #pragma unroll
        for (int i = 0; i < 4; i++) {
            int idx = tid + i*256;
            int r = idx >> 4, c4 = idx & 15;
            *(float4*)&Ks[r*P68 + c4*4] = *(const float4*)&Kg[(size_t)(t0 + r)*DHs + c4*4];
            *(float4*)&Vs[r*P68 + c4*4] = *(const float4*)&Vg[(size_t)(t0 + r)*DHs + c4*4];
        }
        __syncthreads();

        // ---- S = Q @ K^T  (Q pre-scaled by 1/sqrt(DH)) ----
        float s[8][4] = {};
        #pragma unroll
        for (int ks = 0; ks < 8; ks++) {
            int kc = ks*8 + tg;
            unsigned a[4];
            a[0] = f2tf32(Qs[(m0w + g)*P68 + kc]);
            a[1] = f2tf32(Qs[(m0w + g + 8)*P68 + kc]);
            a[2] = f2tf32(Qs[(m0w + g)*P68 + kc + 4]);
            a[3] = f2tf32(Qs[(m0w + g + 8)*P68 + kc + 4]);
            #pragma unroll
            for (int nt = 0; nt < 8; nt++) {
                unsigned bf[2];
                bf[0] = f2tf32(Ks[(nt*8 + g)*P68 + kc]);
                bf[1] = f2tf32(Ks[(nt*8 + g)*P68 + kc + 4]);
                mma_tf32(s[nt], a, bf);
            }
        }

        // ---- online softmax (rows g / g+8 of warp's m-tile; quad = same row) ----
        float rm0 = -1e30f, rm1 = -1e30f;
        #pragma unroll
        for (int nt = 0; nt < 8; nt++) {
            rm0 = fmaxf(rm0, fmaxf(s[nt][0], s[nt][1]));
            rm1 = fmaxf(rm1, fmaxf(s[nt][2], s[nt][3]));
        }
        rm0 = fmaxf(rm0, __shfl_xor_sync(0xffffffffu, rm0, 1));
        rm0 = fmaxf(rm0, __shfl_xor_sync(0xffffffffu, rm0, 2));
        rm1 = fmaxf(rm1, __shfl_xor_sync(0xffffffffu, rm1, 1));
        rm1 = fmaxf(rm1, __shfl_xor_sync(0xffffffffu, rm1, 2));

        float mn0 = fmaxf(m0, rm0), mn1 = fmaxf(m1, rm1);
        float al0 = __expf(m0 - mn0), al1 = __expf(m1 - mn1);
        m0 = mn0; m1 = mn1;

        float rs0 = 0.0f, rs1 = 0.0f;
        #pragma unroll
        for (int nt = 0; nt < 8; nt++) {
            s[nt][0] = __expf(s[nt][0] - m0);
            s[nt][1] = __expf(s[nt][1] - m0);
            s[nt][2] = __expf(s[nt][2] - m1);
            s[nt][3] = __expf(s[nt][3] - m1);
            rs0 += s[nt][0] + s[nt][1];
            rs1 += s[nt][2] + s[nt][3];
        }
        rs0 += __shfl_xor_sync(0xffffffffu, rs0, 1);
        rs0 += __shfl_xor_sync(0xffffffffu, rs0, 2);
        rs1 += __shfl_xor_sync(0xffffffffu, rs1, 1);
        rs1 += __shfl_xor_sync(0xffffffffu, rs1, 2);

        l0 = l0 * al0 + rs0;
        l1 = l1 * al1 + rs1;
        #pragma unroll
        for (int nt = 0; nt < 8; nt++) {
            o[nt][0] *= al0; o[nt][1] *= al0;
            o[nt][2] *= al1; o[nt][3] *= al1;
        }

        // ---- P -> smem (warp-local rows only) ----
        #pragma unroll
        for (int nt = 0; nt < 8; nt++) {
            float2 p01 = make_float2(s[nt][0], s[nt][1]);
            float2 p23 = make_float2(s[nt][2], s[nt][3]);
            *(float2*)&Ps[(m0w + g)*P68 + nt*8 + 2*tg]     = p01;
            *(float2*)&Ps[(m0w + g + 8)*P68 + nt*8 + 2*tg] = p23;
        }
        __syncwarp();

        // ---- O += P @ V ----
        #pragma unroll
        for (int ks = 0; ks < 8; ks++) {
            int kc = ks*8 + tg;
            unsigned a[4];
            a[0] = f2tf32(Ps[(m0w + g)*P68 + kc]);
            a[1] = f2tf32(Ps[(m0w + g + 8)*P68 + kc]);
            a[2] = f2tf32(Ps[(m0w + g)*P68 + kc + 4]);
            a[3] = f2tf32(Ps[(m0w + g + 8)*P68 + kc + 4]);
            #pragma unroll
            for (int nt = 0; nt < 8; nt++) {
                unsigned bf[2];
                bf[0] = f2tf32(Vs[kc*P68 + nt*8 + g]);
                bf[1] = f2tf32(Vs[(kc + 4)*P68 + nt*8 + g]);
                mma_tf32(o[nt], a, bf);
            }
        }
    }

    // ---- normalize + write O in [B,S,H*DH] ----
    float inv0 = 1.0f / l0, inv1 = 1.0f / l1;
    #pragma unroll
    for (int nt = 0; nt < 8; nt++) {
        int col = h*DHs + nt*8 + 2*tg;
        int qa = q0 + m0w + g;
        float2 va = make_float2(o[nt][0]*inv0, o[nt][1]*inv0);
        float2 vb = make_float2(o[nt][2]*inv1, o[nt][3]*inv1);
        *(float2*)&O[((size_t)(b*Ssz + qa)) * Dsz + col]     = va;
        *(float2*)&O[((size_t)(b*Ssz + qa + 8)) * Dsz + col] = vb;
    }
}

// ---------------------------------------------------------------------------

extern "C" void kernel_launch(void* const* d_in, const int* in_sizes, int n_in,
                              void* d_out, int out_size)
{
    (void)in_sizes; (void)n_in; (void)out_size;
    const float* queries = (const float*)d_in[0];
    const float* keys    = (const float*)d_in[1];
    const float* values  = (const float*)d_in[2];
    const float* Wq = (const float*)d_in[3];
    const float* bq = (const float*)d_in[4];
    const float* Wk = (const float*)d_in[5];
    const float* bk = (const float*)d_in[6];
    const float* Wv = (const float*)d_in[7];
    const float* bv = (const float*)d_in[8];
    const float* Wo = (const float*)d_in[9];
    const float* bo = (const float*)d_in[10];
    float* out = (float*)d_out;

    void *pq, *pk, *pv, *po;
    cudaGetSymbolAddress(&pq, g_q);
    cudaGetSymbolAddress(&pk, g_k);
    cudaGetSymbolAddress(&pv, g_v);
    cudaGetSymbolAddress(&po, g_o);

    cudaFuncSetAttribute(gemm_tf32<0>, cudaFuncAttributeMaxDynamicSharedMemorySize, GEMM_SMEM);
    cudaFuncSetAttribute(gemm_tf32<1>, cudaFuncAttributeMaxDynamicSharedMemorySize, GEMM_SMEM);
    cudaFuncSetAttribute(attn_mma,     cudaFuncAttributeMaxDynamicSharedMemorySize, ATTN_SMEM);

    dim3 ggrid(Dsz/128, Mrows/128);   // (8, 32)
    const float qscale = 0.125f;      // 1/sqrt(64)

    gemm_tf32<1><<<ggrid, 256, GEMM_SMEM>>>(queries, Wq, bq, (float*)pq, qscale);
    gemm_tf32<1><<<ggrid, 256, GEMM_SMEM>>>(keys,    Wk, bk, (float*)pk, 1.0f);
    gemm_tf32<1><<<ggrid, 256, GEMM_SMEM>>>(values,  Wv, bv, (float*)pv, 1.0f);

    dim3 agrid(Ssz/128, Hn, Bsz);     // (16, 16, 2)
    attn_mma<<<agrid, 256, ATTN_SMEM>>>((const float*)pq, (const float*)pk,
                                        (const float*)pv, (float*)po);

    gemm_tf32<0><<<ggrid, 256, GEMM_SMEM>>>((const float*)po, Wo, bo, out, 1.0f);
}